// round 1
// baseline (speedup 1.0000x reference)
#include <cuda_runtime.h>
#include <cuda_bf16.h>
#include <cstdint>

// Problem constants
#define BB   256
#define TT   512
#define DD   300
#define HH   128
#define G4   512          // 4*H
#define CC   6

// ---------------- scratch (device globals: allocation-free) ----------------
__device__ float g_gx[(size_t)TT * BB * G4];   // [t][b][g]  256 MB
__device__ float g_h[BB * HH];                 // final hidden

// ======================================================================
// Kernel 1: gx[t][b][g] = sum_d x[b][t][d] * W_ih[g][d] + b_ih[g] + b_hh[g]
// M = T*B = 131072 (row m = t*256 + b), N = 512, K = 300
// 64x64 tile, 256 threads, 4x4 micro-tile, BK=16, reg-prefetch pipeline.
// ======================================================================
__global__ void __launch_bounds__(256) gx_kernel(
    const float* __restrict__ x,
    const float* __restrict__ W_ih,
    const float* __restrict__ b_ih,
    const float* __restrict__ b_hh)
{
    __shared__ float As[16 * 68];
    __shared__ float Bs[16 * 68];

    const int tid = threadIdx.x;
    const int m0  = blockIdx.x * 64;
    const int n0  = blockIdx.y * 64;
    const int t   = m0 >> 8;           // m0 multiple of 64, B=256 -> tile within one t
    const int b0  = m0 & 255;

    const int lm  = tid >> 2;          // 0..63 row within tile
    const int lk4 = tid & 3;           // float4 slot in K

    const float* aptr = x + (size_t)(b0 + lm) * ((size_t)TT * DD) + (size_t)t * DD;
    const float* bptr = W_ih + (size_t)(n0 + lm) * DD;

    const int ty = tid >> 4;           // 0..15  (row group)
    const int tx = tid & 15;           // 0..15  (col group)

    float acc[4][4];
#pragma unroll
    for (int i = 0; i < 4; ++i)
#pragma unroll
        for (int j = 0; j < 4; ++j) acc[i][j] = 0.f;

    float4 ra, rb;
    {
        int kk = lk4 * 4;
        ra = (kk < DD) ? *reinterpret_cast<const float4*>(aptr + kk) : make_float4(0,0,0,0);
        rb = (kk < DD) ? *reinterpret_cast<const float4*>(bptr + kk) : make_float4(0,0,0,0);
    }

    for (int k0 = 0; k0 < DD; k0 += 16) {
        // stage current regs -> smem (transposed [k][m], pad 68)
        As[(lk4*4+0)*68 + lm] = ra.x;
        As[(lk4*4+1)*68 + lm] = ra.y;
        As[(lk4*4+2)*68 + lm] = ra.z;
        As[(lk4*4+3)*68 + lm] = ra.w;
        Bs[(lk4*4+0)*68 + lm] = rb.x;
        Bs[(lk4*4+1)*68 + lm] = rb.y;
        Bs[(lk4*4+2)*68 + lm] = rb.z;
        Bs[(lk4*4+3)*68 + lm] = rb.w;
        __syncthreads();

        // prefetch next K slab
        int kn = k0 + 16 + lk4 * 4;
        if (k0 + 16 < DD) {
            ra = (kn < DD) ? *reinterpret_cast<const float4*>(aptr + kn) : make_float4(0,0,0,0);
            rb = (kn < DD) ? *reinterpret_cast<const float4*>(bptr + kn) : make_float4(0,0,0,0);
        }

#pragma unroll
        for (int k = 0; k < 16; ++k) {
            float4 a4 = *reinterpret_cast<const float4*>(&As[k*68 + ty*4]);
            float4 b4 = *reinterpret_cast<const float4*>(&Bs[k*68 + tx*4]);
            const float av[4] = {a4.x, a4.y, a4.z, a4.w};
            const float bv[4] = {b4.x, b4.y, b4.z, b4.w};
#pragma unroll
            for (int i = 0; i < 4; ++i)
#pragma unroll
                for (int j = 0; j < 4; ++j)
                    acc[i][j] += av[i] * bv[j];
        }
        __syncthreads();
    }

    // epilogue: add bias, write gx
    float bias[4];
#pragma unroll
    for (int j = 0; j < 4; ++j) {
        int n = n0 + tx*4 + j;
        bias[j] = b_ih[n] + b_hh[n];
    }
#pragma unroll
    for (int i = 0; i < 4; ++i) {
        int m = m0 + ty*4 + i;
        float4 v = make_float4(acc[i][0] + bias[0], acc[i][1] + bias[1],
                               acc[i][2] + bias[2], acc[i][3] + bias[3]);
        *reinterpret_cast<float4*>(&g_gx[(size_t)m * G4 + n0 + tx*4]) = v;
    }
}

// ======================================================================
// Kernel 2: persistent LSTM recurrence. 64 blocks x 4 batches, 128 threads.
// Thread tid owns gate rows {tid, tid+128, tid+256, tid+384} = (i,f,g,o) of
// hidden unit k=tid -> no gate exchange needed. W_hh streamed from L2 each
// step in 4 j-chunks (512 rows x 32 cols), cp.async double-buffered.
// ======================================================================
#define NBATCH    4
#define WS_STRIDE 36                          // 32 j + pad, 144B rows (16B aligned)
#define WS_FLOATS (G4 * WS_STRIDE)            // per buffer
#define WS_BYTES  (WS_FLOATS * 4)             // 73728
#define SMEM_K2   (2 * WS_BYTES + HH * 16)    // + h_s (float4 per k)

__device__ __forceinline__ void cp_async16(void* smem_dst, const void* gsrc) {
    uint32_t sa = static_cast<uint32_t>(__cvta_generic_to_shared(smem_dst));
    asm volatile("cp.async.cg.shared.global [%0], [%1], 16;\n" :: "r"(sa), "l"(gsrc));
}
__device__ __forceinline__ void cp_commit() { asm volatile("cp.async.commit_group;\n" ::: "memory"); }

__device__ __forceinline__ float sigf(float x) {
    return 1.f / (1.f + __expf(-x));
}
__device__ __forceinline__ float tanhf_fast(float x) {
    float e = __expf(-2.f * fabsf(x));        // in (0,1], no overflow
    float r = (1.f - e) / (1.f + e);
    return copysignf(r, x);
}

__device__ __forceinline__ void copy_chunk(float* ws, int chunk, int buf,
                                           const float* __restrict__ W_hh, int tid) {
    float* dst = ws + buf * WS_FLOATS;
    const float* src = W_hh + chunk * 32;
#pragma unroll
    for (int it = 0; it < 8; ++it) {
        int idx = it * 128 + tid;             // 0..1023 -> 512 rows x 8 quads... (4096 total/4)
        int g = idx >> 3;                     // need 512 rows x 8 quads = 4096; do x4 below
        int q = idx & 7;
        cp_async16(dst + g * WS_STRIDE + q * 4, src + (size_t)g * HH + q * 4);
        // rows 0..127 covered; remaining rows via extra iterations:
        cp_async16(dst + (g + 128) * WS_STRIDE + q * 4, src + (size_t)(g + 128) * HH + q * 4);
        cp_async16(dst + (g + 256) * WS_STRIDE + q * 4, src + (size_t)(g + 256) * HH + q * 4);
        cp_async16(dst + (g + 384) * WS_STRIDE + q * 4, src + (size_t)(g + 384) * HH + q * 4);
    }
}

__global__ void __launch_bounds__(128, 1) lstm_kernel(
    const float* __restrict__ W_hh,
    const int*   __restrict__ lengths)
{
    extern __shared__ char smem[];
    float*  ws  = reinterpret_cast<float*>(smem);
    float4* hs4 = reinterpret_cast<float4*>(smem + 2 * WS_BYTES);   // hs4[k] = h of 4 batches

    const int tid = threadIdx.x;
    const int b0  = blockIdx.x * NBATCH;

    int len[NBATCH];
#pragma unroll
    for (int bi = 0; bi < NBATCH; ++bi) len[bi] = lengths[b0 + bi];

    float creg[NBATCH] = {0.f, 0.f, 0.f, 0.f};
    float hreg[NBATCH] = {0.f, 0.f, 0.f, 0.f};
    hs4[tid] = make_float4(0.f, 0.f, 0.f, 0.f);

    copy_chunk(ws, 0, 0, W_hh, tid); cp_commit();
    copy_chunk(ws, 1, 1, W_hh, tid); cp_commit();
    __syncthreads();

    for (int t = 0; t < TT; ++t) {
        float acc[4][NBATCH];
        const float* gxrow = g_gx + (size_t)(t * BB + b0) * G4;
#pragma unroll
        for (int gi = 0; gi < 4; ++gi)
#pragma unroll
            for (int bi = 0; bi < NBATCH; ++bi)
                acc[gi][bi] = gxrow[(size_t)bi * G4 + gi * HH + tid];

#pragma unroll
        for (int c = 0; c < 4; ++c) {
            asm volatile("cp.async.wait_group 1;\n" ::: "memory");
            __syncthreads();
            const float* wb = ws + (c & 1) * WS_FLOATS;
#pragma unroll
            for (int j4 = 0; j4 < 8; ++j4) {
                float4 hv[4];
#pragma unroll
                for (int jj = 0; jj < 4; ++jj)
                    hv[jj] = hs4[c * 32 + j4 * 4 + jj];
                float4 wv[4];
#pragma unroll
                for (int gi = 0; gi < 4; ++gi)
                    wv[gi] = *reinterpret_cast<const float4*>(
                        wb + (tid + gi * HH) * WS_STRIDE + j4 * 4);
#pragma unroll
                for (int gi = 0; gi < 4; ++gi) {
                    const float w[4] = {wv[gi].x, wv[gi].y, wv[gi].z, wv[gi].w};
#pragma unroll
                    for (int jj = 0; jj < 4; ++jj) {
                        const float hvv[4] = {hv[jj].x, hv[jj].y, hv[jj].z, hv[jj].w};
#pragma unroll
                        for (int bi = 0; bi < NBATCH; ++bi)
                            acc[gi][bi] += w[jj] * hvv[bi];
                    }
                }
            }
            __syncthreads();
            copy_chunk(ws, (c + 2) & 3, c & 1, W_hh, tid); cp_commit();
        }

        // elementwise: thread owns hidden unit k=tid for all 4 batches
#pragma unroll
        for (int bi = 0; bi < NBATCH; ++bi) {
            float ig = sigf(acc[0][bi]);
            float fg = sigf(acc[1][bi]);
            float gg = tanhf_fast(acc[2][bi]);
            float og = sigf(acc[3][bi]);
            float cn = fg * creg[bi] + ig * gg;
            float hn = og * tanhf_fast(cn);
            if (t < len[bi]) { creg[bi] = cn; hreg[bi] = hn; }
        }
        hs4[tid] = make_float4(hreg[0], hreg[1], hreg[2], hreg[3]);
        // visibility guaranteed by the sync at the top of next step's chunk 0
    }

    asm volatile("cp.async.wait_group 0;\n" ::: "memory");
#pragma unroll
    for (int bi = 0; bi < NBATCH; ++bi)
        g_h[(b0 + bi) * HH + tid] = hreg[bi];
}

// ======================================================================
// Kernel 3: out[b][c] = h[b] . fc_w[c] + fc_b[c]   (256 x 6)
// ======================================================================
__global__ void __launch_bounds__(256) fc_kernel(
    const float* __restrict__ fc_w,
    const float* __restrict__ fc_b,
    float* __restrict__ out)
{
    __shared__ float wsm[CC * HH];
    __shared__ float bsm[CC];
    int tid = threadIdx.x;
    for (int i = tid; i < CC * HH; i += 256) wsm[i] = fc_w[i];
    if (tid < CC) bsm[tid] = fc_b[tid];
    __syncthreads();

    float s[CC];
#pragma unroll
    for (int c = 0; c < CC; ++c) s[c] = bsm[c];
    const float* h = g_h + tid * HH;
#pragma unroll 8
    for (int k = 0; k < HH; ++k) {
        float hk = h[k];
#pragma unroll
        for (int c = 0; c < CC; ++c) s[c] += hk * wsm[c * HH + k];
    }
#pragma unroll
    for (int c = 0; c < CC; ++c) out[tid * CC + c] = s[c];
}

// ======================================================================
extern "C" void kernel_launch(void* const* d_in, const int* in_sizes, int n_in,
                              void* d_out, int out_size)
{
    const float* x     = (const float*)d_in[0];
    const float* W_ih  = (const float*)d_in[1];
    const float* W_hh  = (const float*)d_in[2];
    const float* b_ih  = (const float*)d_in[3];
    const float* b_hh  = (const float*)d_in[4];
    const float* fc_w  = (const float*)d_in[5];
    const float* fc_b  = (const float*)d_in[6];
    const int*   lens  = (const int*)d_in[7];
    float* out = (float*)d_out;

    cudaFuncSetAttribute(lstm_kernel, cudaFuncAttributeMaxDynamicSharedMemorySize, SMEM_K2);

    dim3 g1((TT * BB) / 64, G4 / 64);
    gx_kernel<<<g1, 256>>>(x, W_ih, b_ih, b_hh);

    lstm_kernel<<<BB / NBATCH, 128, SMEM_K2>>>(W_hh, lens);

    fc_kernel<<<1, 256>>>(fc_w, fc_b, out);
}

// round 2
// speedup vs baseline: 2.5444x; 2.5444x over previous
#include <cuda_runtime.h>
#include <cuda_bf16.h>
#include <cstdint>

// Problem constants
#define BB   256
#define TT   512
#define DD   300
#define HH   128
#define G4   512          // 4*H
#define CC   6

// ---------------- scratch (device globals: allocation-free) ----------------
__device__ float g_gx[(size_t)TT * BB * G4];   // [t][b][g]
__device__ float g_h[BB * HH];                 // final hidden

// ======================================================================
// Kernel 1: gx[t][b][g] = sum_d x[b][t][d] * W_ih[g][d] + b_ih[g] + b_hh[g]
// M = T*B = 131072 (row m = t*256 + b), N = 512, K = 300
// 128x128 tile, 256 threads, 8x8 micro-tile, BK=8, reg-prefetch pipeline.
// ======================================================================
#define K1_STRIDE 132   // smem row stride (words), 528B = 16B aligned, bank-safe

__global__ void __launch_bounds__(256, 2) gx_kernel(
    const float* __restrict__ x,
    const float* __restrict__ W_ih,
    const float* __restrict__ b_ih,
    const float* __restrict__ b_hh)
{
    __shared__ float As[8 * K1_STRIDE];
    __shared__ float Bs[8 * K1_STRIDE];

    const int tid = threadIdx.x;
    const int m0  = blockIdx.x * 128;
    const int n0  = blockIdx.y * 128;
    const int t   = m0 >> 8;           // 128 rows stay within one t (B=256)
    const int b0  = m0 & 255;

    // loader mapping: each thread loads one float4 of A and one of B per slab
    const int lrow = tid >> 1;         // 0..127
    const int lkq  = tid & 1;          // float4 slot within BK=8

    const float* aptr = x    + (size_t)(b0 + lrow) * ((size_t)TT * DD) + (size_t)t * DD;
    const float* bptr = W_ih + (size_t)(n0 + lrow) * DD;

    // compute mapping: 8x8 micro-tile
    const int ty = tid >> 4;           // 0..15 -> rows ty*8..+7
    const int tx = tid & 15;           // 0..15 -> cols tx*8..+7

    float acc[8][8];
#pragma unroll
    for (int i = 0; i < 8; ++i)
#pragma unroll
        for (int j = 0; j < 8; ++j) acc[i][j] = 0.f;

    float4 ra, rb;
    {
        int kk = lkq * 4;
        ra = *reinterpret_cast<const float4*>(aptr + kk);
        rb = *reinterpret_cast<const float4*>(bptr + kk);
    }

    for (int k0 = 0; k0 < DD; k0 += 8) {
        // stage current regs -> smem transposed [k][row]
        const int kb = lkq * 4;
        As[(kb+0)*K1_STRIDE + lrow] = ra.x;
        As[(kb+1)*K1_STRIDE + lrow] = ra.y;
        As[(kb+2)*K1_STRIDE + lrow] = ra.z;
        As[(kb+3)*K1_STRIDE + lrow] = ra.w;
        Bs[(kb+0)*K1_STRIDE + lrow] = rb.x;
        Bs[(kb+1)*K1_STRIDE + lrow] = rb.y;
        Bs[(kb+2)*K1_STRIDE + lrow] = rb.z;
        Bs[(kb+3)*K1_STRIDE + lrow] = rb.w;
        __syncthreads();

        // prefetch next slab (K=300 is a multiple of 4 -> float4-safe guard)
        int kn = k0 + 8 + lkq * 4;
        if (k0 + 8 < DD) {
            ra = (kn < DD) ? *reinterpret_cast<const float4*>(aptr + kn) : make_float4(0,0,0,0);
            rb = (kn < DD) ? *reinterpret_cast<const float4*>(bptr + kn) : make_float4(0,0,0,0);
        }

#pragma unroll
        for (int k = 0; k < 8; ++k) {
            float av[8], bv[8];
            *reinterpret_cast<float4*>(&av[0]) = *reinterpret_cast<const float4*>(&As[k*K1_STRIDE + ty*8]);
            *reinterpret_cast<float4*>(&av[4]) = *reinterpret_cast<const float4*>(&As[k*K1_STRIDE + ty*8 + 4]);
            *reinterpret_cast<float4*>(&bv[0]) = *reinterpret_cast<const float4*>(&Bs[k*K1_STRIDE + tx*8]);
            *reinterpret_cast<float4*>(&bv[4]) = *reinterpret_cast<const float4*>(&Bs[k*K1_STRIDE + tx*8 + 4]);
#pragma unroll
            for (int i = 0; i < 8; ++i)
#pragma unroll
                for (int j = 0; j < 8; ++j)
                    acc[i][j] += av[i] * bv[j];
        }
        __syncthreads();
    }

    // epilogue
    float bias[8];
#pragma unroll
    for (int j = 0; j < 8; ++j) {
        int n = n0 + tx*8 + j;
        bias[j] = b_ih[n] + b_hh[n];
    }
#pragma unroll
    for (int i = 0; i < 8; ++i) {
        int m = m0 + ty*8 + i;
        float4 v0 = make_float4(acc[i][0]+bias[0], acc[i][1]+bias[1], acc[i][2]+bias[2], acc[i][3]+bias[3]);
        float4 v1 = make_float4(acc[i][4]+bias[4], acc[i][5]+bias[5], acc[i][6]+bias[6], acc[i][7]+bias[7]);
        float* orow = &g_gx[(size_t)m * G4 + n0 + tx*8];
        *reinterpret_cast<float4*>(orow)     = v0;
        *reinterpret_cast<float4*>(orow + 4) = v1;
    }
}

// ======================================================================
// Kernel 2: persistent LSTM recurrence. 128 blocks x 2 batches, 128 threads.
// Thread tid owns gate rows {tid, 128+tid, 256+tid, 384+tid} = (i,f,g,o) of
// hidden unit k = tid. Gates i,f,g resident in smem (padded stride 132);
// gate o resident in 128 REGISTERS per thread. Zero W traffic per step.
// h double-buffered in smem -> one __syncthreads per step.
// ======================================================================
#define NBATCH 2
#define WRES_ROWS 384
#define WSTRIDE   132                              // words; 528B, bank-conflict-free
#define SMEM_LSTM (WRES_ROWS * WSTRIDE * 4 + 2 * HH * 8)   // 202752 + 2048 = 204800

__device__ __forceinline__ float sigf(float x) {
    return 1.f / (1.f + __expf(-x));
}
__device__ __forceinline__ float tanhf_fast(float x) {
    float e = __expf(-2.f * fabsf(x));        // in (0,1], no overflow
    float r = (1.f - e) / (1.f + e);
    return copysignf(r, x);
}

__global__ void __launch_bounds__(128, 1) lstm_kernel(
    const float* __restrict__ W_hh,
    const int*   __restrict__ lengths)
{
    extern __shared__ float smem[];
    float*  Wr = smem;                                         // [384][132]
    float2* hs = reinterpret_cast<float2*>(smem + WRES_ROWS * WSTRIDE); // [2][128]

    const int tid = threadIdx.x;
    const int b0  = blockIdx.x * NBATCH;

    // ---- load resident W (gates i,f,g: rows 0..383) ----
    for (int i = tid; i < WRES_ROWS * (HH/4); i += 128) {
        int row = i >> 5;           // /32 float4s per row
        int q   = i & 31;
        float4 v = *reinterpret_cast<const float4*>(&W_hh[(size_t)row * HH + q * 4]);
        *reinterpret_cast<float4*>(&Wr[row * WSTRIDE + q * 4]) = v;
    }

    // ---- gate o (rows 384..511) into registers ----
    float ow[HH];
#pragma unroll
    for (int q = 0; q < 32; ++q) {
        float4 v = *reinterpret_cast<const float4*>(&W_hh[(size_t)(384 + tid) * HH + q * 4]);
        ow[q*4+0] = v.x; ow[q*4+1] = v.y; ow[q*4+2] = v.z; ow[q*4+3] = v.w;
    }

    const int len0 = lengths[b0];
    const int len1 = lengths[b0 + 1];

    float c0 = 0.f, c1 = 0.f, h0 = 0.f, h1 = 0.f;
    hs[tid]      = make_float2(0.f, 0.f);   // buffer 0
    hs[HH + tid] = make_float2(0.f, 0.f);   // buffer 1
    __syncthreads();

    // prefetch gx for t=0
    float gxc[4][2];
    {
        const float* gxrow = g_gx + (size_t)b0 * G4;
#pragma unroll
        for (int gi = 0; gi < 4; ++gi) {
            gxc[gi][0] = gxrow[gi * HH + tid];
            gxc[gi][1] = gxrow[G4 + gi * HH + tid];
        }
    }

    for (int t = 0; t < TT; ++t) {
        // prefetch next step's gx (independent of h -> hides L2/DRAM latency)
        float gxn[4][2];
        if (t + 1 < TT) {
            const float* gxrow = g_gx + (size_t)((t + 1) * BB + b0) * G4;
#pragma unroll
            for (int gi = 0; gi < 4; ++gi) {
                gxn[gi][0] = gxrow[gi * HH + tid];
                gxn[gi][1] = gxrow[G4 + gi * HH + tid];
            }
        }

        const float2* hb = hs + (t & 1) * HH;

#pragma unroll
        for (int j4 = 0; j4 < 32; ++j4) {
            // 4 j-values x 2 batches of h (broadcast loads)
            float2 hv[4];
            *reinterpret_cast<float4*>(&hv[0]) = *reinterpret_cast<const float4*>(&hb[j4*4]);
            *reinterpret_cast<float4*>(&hv[2]) = *reinterpret_cast<const float4*>(&hb[j4*4+2]);

            // resident gates i,f,g
#pragma unroll
            for (int gi = 0; gi < 3; ++gi) {
                float4 w = *reinterpret_cast<const float4*>(&Wr[(gi * HH + tid) * WSTRIDE + j4 * 4]);
                gxc[gi][0] += w.x * hv[0].x + w.y * hv[1].x + w.z * hv[2].x + w.w * hv[3].x;
                gxc[gi][1] += w.x * hv[0].y + w.y * hv[1].y + w.z * hv[2].y + w.w * hv[3].y;
            }
            // register-resident gate o
            gxc[3][0] += ow[j4*4+0] * hv[0].x + ow[j4*4+1] * hv[1].x
                       + ow[j4*4+2] * hv[2].x + ow[j4*4+3] * hv[3].x;
            gxc[3][1] += ow[j4*4+0] * hv[0].y + ow[j4*4+1] * hv[1].y
                       + ow[j4*4+2] * hv[2].y + ow[j4*4+3] * hv[3].y;
        }

        // elementwise
        {
            float ig = sigf(gxc[0][0]);
            float fg = sigf(gxc[1][0]);
            float gg = tanhf_fast(gxc[2][0]);
            float og = sigf(gxc[3][0]);
            float cn = fg * c0 + ig * gg;
            float hn = og * tanhf_fast(cn);
            if (t < len0) { c0 = cn; h0 = hn; }
        }
        {
            float ig = sigf(gxc[0][1]);
            float fg = sigf(gxc[1][1]);
            float gg = tanhf_fast(gxc[2][1]);
            float og = sigf(gxc[3][1]);
            float cn = fg * c1 + ig * gg;
            float hn = og * tanhf_fast(cn);
            if (t < len1) { c1 = cn; h1 = hn; }
        }

        // write h into the other buffer, one barrier per step
        hs[((t + 1) & 1) * HH + tid] = make_float2(h0, h1);
        __syncthreads();

#pragma unroll
        for (int gi = 0; gi < 4; ++gi) {
            gxc[gi][0] = gxn[gi][0];
            gxc[gi][1] = gxn[gi][1];
        }
    }

    g_h[(b0 + 0) * HH + tid] = h0;
    g_h[(b0 + 1) * HH + tid] = h1;
}

// ======================================================================
// Kernel 3: out[b][c] = h[b] . fc_w[c] + fc_b[c]   (256 x 6)
// ======================================================================
__global__ void __launch_bounds__(256) fc_kernel(
    const float* __restrict__ fc_w,
    const float* __restrict__ fc_b,
    float* __restrict__ out)
{
    __shared__ float wsm[CC * HH];
    __shared__ float bsm[CC];
    int tid = threadIdx.x;
    for (int i = tid; i < CC * HH; i += 256) wsm[i] = fc_w[i];
    if (tid < CC) bsm[tid] = fc_b[tid];
    __syncthreads();

    float s[CC];
#pragma unroll
    for (int c = 0; c < CC; ++c) s[c] = bsm[c];
    const float* h = g_h + tid * HH;
#pragma unroll 8
    for (int k = 0; k < HH; ++k) {
        float hk = h[k];
#pragma unroll
        for (int c = 0; c < CC; ++c) s[c] += hk * wsm[c * HH + k];
    }
#pragma unroll
    for (int c = 0; c < CC; ++c) out[tid * CC + c] = s[c];
}

// ======================================================================
extern "C" void kernel_launch(void* const* d_in, const int* in_sizes, int n_in,
                              void* d_out, int out_size)
{
    const float* x     = (const float*)d_in[0];
    const float* W_ih  = (const float*)d_in[1];
    const float* W_hh  = (const float*)d_in[2];
    const float* b_ih  = (const float*)d_in[3];
    const float* b_hh  = (const float*)d_in[4];
    const float* fc_w  = (const float*)d_in[5];
    const float* fc_b  = (const float*)d_in[6];
    const int*   lens  = (const int*)d_in[7];
    float* out = (float*)d_out;

    cudaFuncSetAttribute(lstm_kernel, cudaFuncAttributeMaxDynamicSharedMemorySize, SMEM_LSTM);

    dim3 g1((TT * BB) / 128, G4 / 128);
    gx_kernel<<<g1, 256>>>(x, W_ih, b_ih, b_hh);

    lstm_kernel<<<BB / NBATCH, 128, SMEM_LSTM>>>(W_hh, lens);

    fc_kernel<<<1, 256>>>(fc_w, fc_b, out);
}

// round 3
// speedup vs baseline: 2.7827x; 1.0937x over previous
#include <cuda_runtime.h>
#include <cuda_bf16.h>
#include <cstdint>

// Problem constants
#define BB   256
#define TT   512
#define DD   300
#define HH   128
#define G4   512          // 4*H
#define CC   6

// ---------------- scratch (device globals: allocation-free) ----------------
__device__ float g_gx[(size_t)TT * BB * G4];   // [t][b][g]
__device__ float g_h[BB * HH];                 // final hidden

// ======================================================================
// Kernel 1: gx[t][b][g] = sum_d x[b][t][d] * W_ih[g][d] + b_ih[g] + b_hh[g]
// M = T*B = 131072 (row m = t*256 + b), N = 512, K = 300
// 128x128 tile, 256 threads, 8x8 micro-tile SPLIT 4+4 (conflict-free LDS).
// ======================================================================
#define K1_STRIDE 132   // smem row stride (words)

__global__ void __launch_bounds__(256, 2) gx_kernel(
    const float* __restrict__ x,
    const float* __restrict__ W_ih,
    const float* __restrict__ b_ih,
    const float* __restrict__ b_hh)
{
    __shared__ float As[8 * K1_STRIDE];
    __shared__ float Bs[8 * K1_STRIDE];

    const int tid = threadIdx.x;
    const int m0  = blockIdx.x * 128;
    const int n0  = blockIdx.y * 128;
    const int t   = m0 >> 8;           // 128 rows stay within one t (B=256)
    const int b0  = m0 & 255;

    const int lrow = tid >> 1;         // 0..127
    const int lkq  = tid & 1;          // float4 slot within BK=8

    const float* aptr = x    + (size_t)(b0 + lrow) * ((size_t)TT * DD) + (size_t)t * DD;
    const float* bptr = W_ih + (size_t)(n0 + lrow) * DD;

    const int ty = tid >> 4;           // 0..15
    const int tx = tid & 15;           // 0..15

    float acc[8][8];
#pragma unroll
    for (int i = 0; i < 8; ++i)
#pragma unroll
        for (int j = 0; j < 8; ++j) acc[i][j] = 0.f;

    float4 ra, rb;
    {
        int kk = lkq * 4;
        ra = *reinterpret_cast<const float4*>(aptr + kk);
        rb = *reinterpret_cast<const float4*>(bptr + kk);
    }

    for (int k0 = 0; k0 < DD; k0 += 8) {
        const int kb = lkq * 4;
        As[(kb+0)*K1_STRIDE + lrow] = ra.x;
        As[(kb+1)*K1_STRIDE + lrow] = ra.y;
        As[(kb+2)*K1_STRIDE + lrow] = ra.z;
        As[(kb+3)*K1_STRIDE + lrow] = ra.w;
        Bs[(kb+0)*K1_STRIDE + lrow] = rb.x;
        Bs[(kb+1)*K1_STRIDE + lrow] = rb.y;
        Bs[(kb+2)*K1_STRIDE + lrow] = rb.z;
        Bs[(kb+3)*K1_STRIDE + lrow] = rb.w;
        __syncthreads();

        int kn = k0 + 8 + lkq * 4;
        if (k0 + 8 < DD) {
            ra = (kn < DD) ? *reinterpret_cast<const float4*>(aptr + kn) : make_float4(0,0,0,0);
            rb = (kn < DD) ? *reinterpret_cast<const float4*>(bptr + kn) : make_float4(0,0,0,0);
        }

#pragma unroll
        for (int k = 0; k < 8; ++k) {
            float av[8], bv[8];
            // split fragments: 16-byte stride across phase-mates -> conflict-free
            *reinterpret_cast<float4*>(&av[0]) = *reinterpret_cast<const float4*>(&As[k*K1_STRIDE + ty*4]);
            *reinterpret_cast<float4*>(&av[4]) = *reinterpret_cast<const float4*>(&As[k*K1_STRIDE + 64 + ty*4]);
            *reinterpret_cast<float4*>(&bv[0]) = *reinterpret_cast<const float4*>(&Bs[k*K1_STRIDE + tx*4]);
            *reinterpret_cast<float4*>(&bv[4]) = *reinterpret_cast<const float4*>(&Bs[k*K1_STRIDE + 64 + tx*4]);
#pragma unroll
            for (int i = 0; i < 8; ++i)
#pragma unroll
                for (int j = 0; j < 8; ++j)
                    acc[i][j] += av[i] * bv[j];
        }
        __syncthreads();
    }

    // epilogue: rows {ty*4+i, 64+ty*4+i}, cols {tx*4+j, 64+tx*4+j}
    float bias[8];
#pragma unroll
    for (int j = 0; j < 4; ++j) {
        bias[j]     = b_ih[n0 + tx*4 + j]      + b_hh[n0 + tx*4 + j];
        bias[4 + j] = b_ih[n0 + 64 + tx*4 + j] + b_hh[n0 + 64 + tx*4 + j];
    }
#pragma unroll
    for (int half = 0; half < 2; ++half) {
#pragma unroll
        for (int i = 0; i < 4; ++i) {
            int m = m0 + half * 64 + ty*4 + i;
            int ii = half * 4 + i;
            float4 v0 = make_float4(acc[ii][0]+bias[0], acc[ii][1]+bias[1],
                                    acc[ii][2]+bias[2], acc[ii][3]+bias[3]);
            float4 v1 = make_float4(acc[ii][4]+bias[4], acc[ii][5]+bias[5],
                                    acc[ii][6]+bias[6], acc[ii][7]+bias[7]);
            float* orow = &g_gx[(size_t)m * G4 + n0];
            *reinterpret_cast<float4*>(orow + tx*4)      = v0;
            *reinterpret_cast<float4*>(orow + 64 + tx*4) = v1;
        }
    }
}

// ======================================================================
// Kernel 2: persistent LSTM. 128 blocks x 2 batches, 256 threads (8 warps).
// Thread (jg, k): jg = tid>>7 selects j-half [jg*64, jg*64+64), k = tid&127.
// Owns gate rows {k, 128+k, 256+k, 384+k} on its j-half.
// Gates g,o for own half in REGISTERS (128 regs); gates i,f from smem.
// Partial sums reduced via padded smem buffer; 2 barriers/step.
// ======================================================================
#define WRES_ROWS 256                       // gates i,f resident in smem
#define WSTRIDE   132
#define RED_STRIDE 12                       // 48B, 16B-aligned, conflict-free
#define SMEM_LSTM (WRES_ROWS*WSTRIDE*4 + 2*HH*8 + HH*RED_STRIDE*4)

__device__ __forceinline__ float sigf(float x) {
    return 1.f / (1.f + __expf(-x));
}
__device__ __forceinline__ float tanhf_fast(float x) {
    float e = __expf(-2.f * fabsf(x));
    float r = (1.f - e) / (1.f + e);
    return copysignf(r, x);
}

__global__ void __launch_bounds__(256, 1) lstm_kernel(
    const float* __restrict__ W_hh,
    const int*   __restrict__ lengths)
{
    extern __shared__ float smem[];
    float*  Wr  = smem;                                            // [256][132]
    float2* hs  = reinterpret_cast<float2*>(smem + WRES_ROWS*WSTRIDE); // [2][128]
    float*  red = smem + WRES_ROWS*WSTRIDE + 2*HH*2;               // [128][12]

    const int tid = threadIdx.x;
    const int jg  = tid >> 7;          // j-group 0/1
    const int k   = tid & 127;         // hidden unit
    const int jb  = jg * 64;           // j base
    const int b0  = blockIdx.x * 2;

    // ---- resident W: gates i,f (rows 0..255), all j ----
    for (int i = tid; i < WRES_ROWS * (HH/4); i += 256) {
        int row = i >> 5;
        int q   = i & 31;
        float4 v = *reinterpret_cast<const float4*>(&W_hh[(size_t)row * HH + q * 4]);
        *reinterpret_cast<float4*>(&Wr[row * WSTRIDE + q * 4]) = v;
    }

    // ---- register W: gates g,o, own j-half ----
    float wg[64], wo[64];
#pragma unroll
    for (int q = 0; q < 16; ++q) {
        float4 vg = *reinterpret_cast<const float4*>(&W_hh[(size_t)(256 + k) * HH + jb + q*4]);
        float4 vo = *reinterpret_cast<const float4*>(&W_hh[(size_t)(384 + k) * HH + jb + q*4]);
        wg[q*4+0]=vg.x; wg[q*4+1]=vg.y; wg[q*4+2]=vg.z; wg[q*4+3]=vg.w;
        wo[q*4+0]=vo.x; wo[q*4+1]=vo.y; wo[q*4+2]=vo.z; wo[q*4+3]=vo.w;
    }

    const int len0 = lengths[b0];
    const int len1 = lengths[b0 + 1];

    float c0 = 0.f, c1 = 0.f, h0 = 0.f, h1 = 0.f;
    if (jg == 0) {
        hs[k]      = make_float2(0.f, 0.f);
        hs[HH + k] = make_float2(0.f, 0.f);
    }
    __syncthreads();

    float gxc[4][2] = {};
    if (jg == 0) {
        const float* gxrow = g_gx + (size_t)b0 * G4;
#pragma unroll
        for (int gi = 0; gi < 4; ++gi) {
            gxc[gi][0] = gxrow[gi * HH + k];
            gxc[gi][1] = gxrow[G4 + gi * HH + k];
        }
    }

    for (int t = 0; t < TT; ++t) {
        float gxn[4][2] = {};
        if (jg == 0 && t + 1 < TT) {
            const float* gxrow = g_gx + (size_t)((t + 1) * BB + b0) * G4;
#pragma unroll
            for (int gi = 0; gi < 4; ++gi) {
                gxn[gi][0] = gxrow[gi * HH + k];
                gxn[gi][1] = gxrow[G4 + gi * HH + k];
            }
        }

        const float2* hb = hs + (t & 1) * HH + jb;

        float a0b0 = gxc[0][0], a0b1 = gxc[0][1];
        float a1b0 = gxc[1][0], a1b1 = gxc[1][1];
        float a2b0 = gxc[2][0], a2b1 = gxc[2][1];
        float a3b0 = gxc[3][0], a3b1 = gxc[3][1];

#pragma unroll
        for (int j4 = 0; j4 < 16; ++j4) {
            float2 hv[4];
            *reinterpret_cast<float4*>(&hv[0]) = *reinterpret_cast<const float4*>(&hb[j4*4]);
            *reinterpret_cast<float4*>(&hv[2]) = *reinterpret_cast<const float4*>(&hb[j4*4+2]);

            float4 wi = *reinterpret_cast<const float4*>(&Wr[(k)        * WSTRIDE + jb + j4*4]);
            float4 wf = *reinterpret_cast<const float4*>(&Wr[(HH + k)   * WSTRIDE + jb + j4*4]);

            a0b0 += wi.x*hv[0].x + wi.y*hv[1].x + wi.z*hv[2].x + wi.w*hv[3].x;
            a0b1 += wi.x*hv[0].y + wi.y*hv[1].y + wi.z*hv[2].y + wi.w*hv[3].y;
            a1b0 += wf.x*hv[0].x + wf.y*hv[1].x + wf.z*hv[2].x + wf.w*hv[3].x;
            a1b1 += wf.x*hv[0].y + wf.y*hv[1].y + wf.z*hv[2].y + wf.w*hv[3].y;

            a2b0 += wg[j4*4+0]*hv[0].x + wg[j4*4+1]*hv[1].x + wg[j4*4+2]*hv[2].x + wg[j4*4+3]*hv[3].x;
            a2b1 += wg[j4*4+0]*hv[0].y + wg[j4*4+1]*hv[1].y + wg[j4*4+2]*hv[2].y + wg[j4*4+3]*hv[3].y;
            a3b0 += wo[j4*4+0]*hv[0].x + wo[j4*4+1]*hv[1].x + wo[j4*4+2]*hv[2].x + wo[j4*4+3]*hv[3].x;
            a3b1 += wo[j4*4+0]*hv[0].y + wo[j4*4+1]*hv[1].y + wo[j4*4+2]*hv[2].y + wo[j4*4+3]*hv[3].y;
        }

        if (jg == 1) {
            float* r = red + k * RED_STRIDE;
            *reinterpret_cast<float4*>(r)     = make_float4(a0b0, a0b1, a1b0, a1b1);
            *reinterpret_cast<float4*>(r + 4) = make_float4(a2b0, a2b1, a3b0, a3b1);
        }
        __syncthreads();

        if (jg == 0) {
            const float* r = red + k * RED_STRIDE;
            float4 p0 = *reinterpret_cast<const float4*>(r);
            float4 p1 = *reinterpret_cast<const float4*>(r + 4);
            a0b0 += p0.x; a0b1 += p0.y; a1b0 += p0.z; a1b1 += p0.w;
            a2b0 += p1.x; a2b1 += p1.y; a3b0 += p1.z; a3b1 += p1.w;

            {
                float ig = sigf(a0b0), fg = sigf(a1b0);
                float gg = tanhf_fast(a2b0), og = sigf(a3b0);
                float cn = fg * c0 + ig * gg;
                float hn = og * tanhf_fast(cn);
                if (t < len0) { c0 = cn; h0 = hn; }
            }
            {
                float ig = sigf(a0b1), fg = sigf(a1b1);
                float gg = tanhf_fast(a2b1), og = sigf(a3b1);
                float cn = fg * c1 + ig * gg;
                float hn = og * tanhf_fast(cn);
                if (t < len1) { c1 = cn; h1 = hn; }
            }
            hs[((t + 1) & 1) * HH + k] = make_float2(h0, h1);
        }
        __syncthreads();

#pragma unroll
        for (int gi = 0; gi < 4; ++gi) {
            gxc[gi][0] = gxn[gi][0];
            gxc[gi][1] = gxn[gi][1];
        }
    }

    if (jg == 0) {
        g_h[(b0 + 0) * HH + k] = h0;
        g_h[(b0 + 1) * HH + k] = h1;
    }
}

// ======================================================================
// Kernel 3: out[b][c] = h[b] . fc_w[c] + fc_b[c]   (256 x 6)
// ======================================================================
__global__ void __launch_bounds__(256) fc_kernel(
    const float* __restrict__ fc_w,
    const float* __restrict__ fc_b,
    float* __restrict__ out)
{
    __shared__ float wsm[CC * HH];
    __shared__ float bsm[CC];
    int tid = threadIdx.x;
    for (int i = tid; i < CC * HH; i += 256) wsm[i] = fc_w[i];
    if (tid < CC) bsm[tid] = fc_b[tid];
    __syncthreads();

    float s[CC];
#pragma unroll
    for (int c = 0; c < CC; ++c) s[c] = bsm[c];
    const float* h = g_h + tid * HH;
#pragma unroll 8
    for (int kk = 0; kk < HH; ++kk) {
        float hk = h[kk];
#pragma unroll
        for (int c = 0; c < CC; ++c) s[c] += hk * wsm[c * HH + kk];
    }
#pragma unroll
    for (int c = 0; c < CC; ++c) out[tid * CC + c] = s[c];
}

// ======================================================================
extern "C" void kernel_launch(void* const* d_in, const int* in_sizes, int n_in,
                              void* d_out, int out_size)
{
    const float* x     = (const float*)d_in[0];
    const float* W_ih  = (const float*)d_in[1];
    const float* W_hh  = (const float*)d_in[2];
    const float* b_ih  = (const float*)d_in[3];
    const float* b_hh  = (const float*)d_in[4];
    const float* fc_w  = (const float*)d_in[5];
    const float* fc_b  = (const float*)d_in[6];
    const int*   lens  = (const int*)d_in[7];
    float* out = (float*)d_out;

    cudaFuncSetAttribute(lstm_kernel, cudaFuncAttributeMaxDynamicSharedMemorySize, SMEM_LSTM);

    dim3 g1((TT * BB) / 128, G4 / 128);
    gx_kernel<<<g1, 256>>>(x, W_ih, b_ih, b_hh);

    lstm_kernel<<<BB / 2, 256, SMEM_LSTM>>>(W_hh, lens);

    fc_kernel<<<1, 256>>>(fc_w, fc_b, out);
}

// round 4
// speedup vs baseline: 2.8634x; 1.0290x over previous
#include <cuda_runtime.h>
#include <cuda_bf16.h>
#include <cstdint>

// Problem constants
#define BB   256
#define TT   512
#define DD   300
#define HH   128
#define G4   512          // 4*H
#define CC   6

// ---------------- scratch (device globals: allocation-free) ----------------
__device__ float g_gx[(size_t)TT * BB * G4];   // [t][b][g]
__device__ float g_h[BB * HH];                 // final hidden

// ======================================================================
// Kernel 1: gx = x @ W_ih^T + b_ih + b_hh   (unchanged from round 3)
// ======================================================================
#define K1_STRIDE 132

__global__ void __launch_bounds__(256, 2) gx_kernel(
    const float* __restrict__ x,
    const float* __restrict__ W_ih,
    const float* __restrict__ b_ih,
    const float* __restrict__ b_hh)
{
    __shared__ float As[8 * K1_STRIDE];
    __shared__ float Bs[8 * K1_STRIDE];

    const int tid = threadIdx.x;
    const int m0  = blockIdx.x * 128;
    const int n0  = blockIdx.y * 128;
    const int t   = m0 >> 8;
    const int b0  = m0 & 255;

    const int lrow = tid >> 1;
    const int lkq  = tid & 1;

    const float* aptr = x    + (size_t)(b0 + lrow) * ((size_t)TT * DD) + (size_t)t * DD;
    const float* bptr = W_ih + (size_t)(n0 + lrow) * DD;

    const int ty = tid >> 4;
    const int tx = tid & 15;

    float acc[8][8];
#pragma unroll
    for (int i = 0; i < 8; ++i)
#pragma unroll
        for (int j = 0; j < 8; ++j) acc[i][j] = 0.f;

    float4 ra, rb;
    {
        int kk = lkq * 4;
        ra = *reinterpret_cast<const float4*>(aptr + kk);
        rb = *reinterpret_cast<const float4*>(bptr + kk);
    }

    for (int k0 = 0; k0 < DD; k0 += 8) {
        const int kb = lkq * 4;
        As[(kb+0)*K1_STRIDE + lrow] = ra.x;
        As[(kb+1)*K1_STRIDE + lrow] = ra.y;
        As[(kb+2)*K1_STRIDE + lrow] = ra.z;
        As[(kb+3)*K1_STRIDE + lrow] = ra.w;
        Bs[(kb+0)*K1_STRIDE + lrow] = rb.x;
        Bs[(kb+1)*K1_STRIDE + lrow] = rb.y;
        Bs[(kb+2)*K1_STRIDE + lrow] = rb.z;
        Bs[(kb+3)*K1_STRIDE + lrow] = rb.w;
        __syncthreads();

        int kn = k0 + 8 + lkq * 4;
        if (k0 + 8 < DD) {
            ra = (kn < DD) ? *reinterpret_cast<const float4*>(aptr + kn) : make_float4(0,0,0,0);
            rb = (kn < DD) ? *reinterpret_cast<const float4*>(bptr + kn) : make_float4(0,0,0,0);
        }

#pragma unroll
        for (int k = 0; k < 8; ++k) {
            float av[8], bv[8];
            *reinterpret_cast<float4*>(&av[0]) = *reinterpret_cast<const float4*>(&As[k*K1_STRIDE + ty*4]);
            *reinterpret_cast<float4*>(&av[4]) = *reinterpret_cast<const float4*>(&As[k*K1_STRIDE + 64 + ty*4]);
            *reinterpret_cast<float4*>(&bv[0]) = *reinterpret_cast<const float4*>(&Bs[k*K1_STRIDE + tx*4]);
            *reinterpret_cast<float4*>(&bv[4]) = *reinterpret_cast<const float4*>(&Bs[k*K1_STRIDE + 64 + tx*4]);
#pragma unroll
            for (int i = 0; i < 8; ++i)
#pragma unroll
                for (int j = 0; j < 8; ++j)
                    acc[i][j] += av[i] * bv[j];
        }
        __syncthreads();
    }

    float bias[8];
#pragma unroll
    for (int j = 0; j < 4; ++j) {
        bias[j]     = b_ih[n0 + tx*4 + j]      + b_hh[n0 + tx*4 + j];
        bias[4 + j] = b_ih[n0 + 64 + tx*4 + j] + b_hh[n0 + 64 + tx*4 + j];
    }
#pragma unroll
    for (int half = 0; half < 2; ++half) {
#pragma unroll
        for (int i = 0; i < 4; ++i) {
            int m = m0 + half * 64 + ty*4 + i;
            int ii = half * 4 + i;
            float4 v0 = make_float4(acc[ii][0]+bias[0], acc[ii][1]+bias[1],
                                    acc[ii][2]+bias[2], acc[ii][3]+bias[3]);
            float4 v1 = make_float4(acc[ii][4]+bias[4], acc[ii][5]+bias[5],
                                    acc[ii][6]+bias[6], acc[ii][7]+bias[7]);
            float* orow = &g_gx[(size_t)m * G4 + n0];
            *reinterpret_cast<float4*>(orow + tx*4)      = v0;
            *reinterpret_cast<float4*>(orow + 64 + tx*4) = v1;
        }
    }
}

// ======================================================================
// Kernel 2: persistent LSTM. 128 blocks x 2 batches, 512 threads.
// jg = tid>>7 (4 j-groups, 32-j windows), k = tid&127 (hidden unit).
// FMA2 (fma.rn.f32x2) over natural j-pairs: acc lanes = even/odd-j partials.
// Gates g,o: register pairs. Gates i,f: smem pair-transposed Wp[jp][k]
// (lane-consecutive 8B loads, conflict-free). h stored [buf][b][j] (broadcast).
// 3 groups write 8-scalar partials (odd stride 25), group 0 reduces +
// elementwise. 2 barriers/step.
// ======================================================================
#define RSTR    25
#define OFF_WI  0
#define OFF_WF  (64*128*2)                 // 16384 floats
#define OFF_HS  (OFF_WF + 64*128*2)        // 32768
#define OFF_RED (OFF_HS + 512)             // 33280
#define SMEM_LS ((OFF_RED + 128*RSTR) * 4) // 145920 B

__device__ __forceinline__ unsigned long long fma2(unsigned long long a,
                                                   unsigned long long b,
                                                   unsigned long long c) {
    unsigned long long d;
    asm("fma.rn.f32x2 %0, %1, %2, %3;" : "=l"(d) : "l"(a), "l"(b), "l"(c));
    return d;
}
__device__ __forceinline__ unsigned long long pack2(float lo, float hi) {
    unsigned long long r;
    asm("mov.b64 %0, {%1, %2};" : "=l"(r) : "f"(lo), "f"(hi));
    return r;
}
__device__ __forceinline__ float sum2(unsigned long long v) {
    float lo, hi;
    asm("mov.b64 {%0, %1}, %2;" : "=f"(lo), "=f"(hi) : "l"(v));
    return lo + hi;
}
__device__ __forceinline__ float sigf(float x) {
    return 1.f / (1.f + __expf(-x));
}
__device__ __forceinline__ float tanhf_fast(float x) {
    float e = __expf(-2.f * fabsf(x));
    float r = (1.f - e) / (1.f + e);
    return copysignf(r, x);
}

__global__ void __launch_bounds__(512, 1) lstm_kernel(
    const float* __restrict__ W_hh,
    const int*   __restrict__ lengths)
{
    extern __shared__ float sm[];
    float* Wi2 = sm + OFF_WI;     // pair-transposed gate i: [jp 0..63][k 0..127] float2
    float* Wf2 = sm + OFF_WF;     // gate f
    float* hs  = sm + OFF_HS;     // [buf 2][b 2][j 128]
    float* red = sm + OFF_RED;    // [k 128][24] stride 25

    const int tid = threadIdx.x;
    const int jg  = tid >> 7;          // 0..3
    const int k   = tid & 127;
    const int jb  = jg * 32;           // j window base
    const int jbp = jg * 16;           // jp window base
    const int b0  = blockIdx.x * 2;

    // build pair-transposed smem for gates i, f (one-time)
    for (int idx = tid; idx < 8192; idx += 512) {
        int kk = idx >> 6;             // 0..127 (coalesced gmem read across jp)
        int jp = idx & 63;
        float2 vi = *reinterpret_cast<const float2*>(&W_hh[(size_t)kk * HH + jp*2]);
        float2 vf = *reinterpret_cast<const float2*>(&W_hh[(size_t)(HH + kk) * HH + jp*2]);
        *reinterpret_cast<float2*>(&Wi2[(jp*128 + kk)*2]) = vi;
        *reinterpret_cast<float2*>(&Wf2[(jp*128 + kk)*2]) = vf;
    }

    // register pairs for gates g, o on own j-window
    unsigned long long wg2[16], wo2[16];
    {
        const float* gp = &W_hh[(size_t)(2*HH + k) * HH + jb];
        const float* op = &W_hh[(size_t)(3*HH + k) * HH + jb];
#pragma unroll
        for (int m = 0; m < 8; ++m) {
            ulonglong2 a = *reinterpret_cast<const ulonglong2*>(gp + m*4);
            wg2[m*2] = a.x; wg2[m*2+1] = a.y;
            ulonglong2 b = *reinterpret_cast<const ulonglong2*>(op + m*4);
            wo2[m*2] = b.x; wo2[m*2+1] = b.y;
        }
    }

    const int len0 = lengths[b0], len1 = lengths[b0 + 1];
    float c0 = 0.f, c1 = 0.f, h0 = 0.f, h1 = 0.f;
    if (jg == 0) { hs[k] = 0.f; hs[128+k] = 0.f; hs[256+k] = 0.f; hs[384+k] = 0.f; }
    __syncthreads();

    // initial gx (group jg owns gate jg)
    float gxc0, gxc1;
    {
        const float* r = g_gx + (size_t)b0 * G4;
        gxc0 = r[jg*HH + k];
        gxc1 = r[G4 + jg*HH + k];
    }

    for (int t = 0; t < TT; ++t) {
        // prefetch next step's gx (hides latency under the FMA loop)
        float gxn0 = 0.f, gxn1 = 0.f;
        if (t + 1 < TT) {
            const float* r = g_gx + (size_t)((t + 1) * BB + b0) * G4;
            gxn0 = r[jg*HH + k];
            gxn1 = r[G4 + jg*HH + k];
        }

        unsigned long long acc[4][2];
#pragma unroll
        for (int gi = 0; gi < 4; ++gi) {
            acc[gi][0] = pack2((gi == jg) ? gxc0 : 0.f, 0.f);
            acc[gi][1] = pack2((gi == jg) ? gxc1 : 0.f, 0.f);
        }

        const float* hb = hs + (t & 1) * 256;
        const ulonglong2* h0p = reinterpret_cast<const ulonglong2*>(hb + jb);
        const ulonglong2* h1p = reinterpret_cast<const ulonglong2*>(hb + 128 + jb);

#pragma unroll
        for (int q = 0; q < 8; ++q) {
            ulonglong2 hp0 = h0p[q];       // j pairs (jb+4q, +1) and (jb+4q+2, +3), batch 0
            ulonglong2 hp1 = h1p[q];       // batch 1
            unsigned long long wia = *reinterpret_cast<const unsigned long long*>(&Wi2[((jbp + 2*q    )*128 + k)*2]);
            unsigned long long wib = *reinterpret_cast<const unsigned long long*>(&Wi2[((jbp + 2*q + 1)*128 + k)*2]);
            unsigned long long wfa = *reinterpret_cast<const unsigned long long*>(&Wf2[((jbp + 2*q    )*128 + k)*2]);
            unsigned long long wfb = *reinterpret_cast<const unsigned long long*>(&Wf2[((jbp + 2*q + 1)*128 + k)*2]);

            acc[0][0] = fma2(wia, hp0.x, acc[0][0]);
            acc[0][0] = fma2(wib, hp0.y, acc[0][0]);
            acc[0][1] = fma2(wia, hp1.x, acc[0][1]);
            acc[0][1] = fma2(wib, hp1.y, acc[0][1]);

            acc[1][0] = fma2(wfa, hp0.x, acc[1][0]);
            acc[1][0] = fma2(wfb, hp0.y, acc[1][0]);
            acc[1][1] = fma2(wfa, hp1.x, acc[1][1]);
            acc[1][1] = fma2(wfb, hp1.y, acc[1][1]);

            acc[2][0] = fma2(wg2[2*q],   hp0.x, acc[2][0]);
            acc[2][0] = fma2(wg2[2*q+1], hp0.y, acc[2][0]);
            acc[2][1] = fma2(wg2[2*q],   hp1.x, acc[2][1]);
            acc[2][1] = fma2(wg2[2*q+1], hp1.y, acc[2][1]);

            acc[3][0] = fma2(wo2[2*q],   hp0.x, acc[3][0]);
            acc[3][0] = fma2(wo2[2*q+1], hp0.y, acc[3][0]);
            acc[3][1] = fma2(wo2[2*q],   hp1.x, acc[3][1]);
            acc[3][1] = fma2(wo2[2*q+1], hp1.y, acc[3][1]);
        }

        float s00 = sum2(acc[0][0]), s01 = sum2(acc[0][1]);
        float s10 = sum2(acc[1][0]), s11 = sum2(acc[1][1]);
        float s20 = sum2(acc[2][0]), s21 = sum2(acc[2][1]);
        float s30 = sum2(acc[3][0]), s31 = sum2(acc[3][1]);

        if (jg != 0) {
            float* r = &red[k * RSTR + (jg - 1) * 8];
            r[0] = s00; r[1] = s01; r[2] = s10; r[3] = s11;
            r[4] = s20; r[5] = s21; r[6] = s30; r[7] = s31;
        }
        __syncthreads();

        if (jg == 0) {
#pragma unroll
            for (int g2 = 0; g2 < 3; ++g2) {
                const float* r = &red[k * RSTR + g2 * 8];
                s00 += r[0]; s01 += r[1]; s10 += r[2]; s11 += r[3];
                s20 += r[4]; s21 += r[5]; s30 += r[6]; s31 += r[7];
            }
            {
                float ig = sigf(s00), fg = sigf(s10);
                float gg = tanhf_fast(s20), og = sigf(s30);
                float cn = fg * c0 + ig * gg;
                float hn = og * tanhf_fast(cn);
                if (t < len0) { c0 = cn; h0 = hn; }
            }
            {
                float ig = sigf(s01), fg = sigf(s11);
                float gg = tanhf_fast(s21), og = sigf(s31);
                float cn = fg * c1 + ig * gg;
                float hn = og * tanhf_fast(cn);
                if (t < len1) { c1 = cn; h1 = hn; }
            }
            float* hn = hs + ((t + 1) & 1) * 256;
            hn[k] = h0; hn[128 + k] = h1;
        }
        __syncthreads();

        gxc0 = gxn0; gxc1 = gxn1;
    }

    if (jg == 0) {
        g_h[(b0 + 0) * HH + k] = h0;
        g_h[(b0 + 1) * HH + k] = h1;
    }
}

// ======================================================================
// Kernel 3: out[b][c] = h[b] . fc_w[c] + fc_b[c]   (256 x 6)
// ======================================================================
__global__ void __launch_bounds__(256) fc_kernel(
    const float* __restrict__ fc_w,
    const float* __restrict__ fc_b,
    float* __restrict__ out)
{
    __shared__ float wsm[CC * HH];
    __shared__ float bsm[CC];
    int tid = threadIdx.x;
    for (int i = tid; i < CC * HH; i += 256) wsm[i] = fc_w[i];
    if (tid < CC) bsm[tid] = fc_b[tid];
    __syncthreads();

    float s[CC];
#pragma unroll
    for (int c = 0; c < CC; ++c) s[c] = bsm[c];
    const float* h = g_h + tid * HH;
#pragma unroll 8
    for (int kk = 0; kk < HH; ++kk) {
        float hk = h[kk];
#pragma unroll
        for (int c = 0; c < CC; ++c) s[c] += hk * wsm[c * HH + kk];
    }
#pragma unroll
    for (int c = 0; c < CC; ++c) out[tid * CC + c] = s[c];
}

// ======================================================================
extern "C" void kernel_launch(void* const* d_in, const int* in_sizes, int n_in,
                              void* d_out, int out_size)
{
    const float* x     = (const float*)d_in[0];
    const float* W_ih  = (const float*)d_in[1];
    const float* W_hh  = (const float*)d_in[2];
    const float* b_ih  = (const float*)d_in[3];
    const float* b_hh  = (const float*)d_in[4];
    const float* fc_w  = (const float*)d_in[5];
    const float* fc_b  = (const float*)d_in[6];
    const int*   lens  = (const int*)d_in[7];
    float* out = (float*)d_out;

    cudaFuncSetAttribute(lstm_kernel, cudaFuncAttributeMaxDynamicSharedMemorySize, SMEM_LS);

    dim3 g1((TT * BB) / 128, G4 / 128);
    gx_kernel<<<g1, 256>>>(x, W_ih, b_ih, b_hh);

    lstm_kernel<<<BB / 2, 512, SMEM_LS>>>(W_hh, lens);

    fc_kernel<<<1, 256>>>(fc_w, fc_b, out);
}